// round 1
// baseline (speedup 1.0000x reference)
#include <cuda_runtime.h>
#include <cuda_bf16.h>
#include <math_constants.h>

#define N_NODES 50000
#define N_EDGES 800000
#define NE_TOT  (N_EDGES + N_NODES)   // edges + self loops = 850000
#define IN_CH   128
#define OUT_CH  128
#define HEADS   4
#define HEAD_DIM 32
#define NEG_SLOPE 0.2f
#define LN_EPS 1e-5f

// ---------------- scratch (static device allocations; no cudaMalloc allowed) ----
__device__ float    g_xl[N_NODES * OUT_CH];      // 25.6 MB
__device__ float    g_xr[N_NODES * OUT_CH];      // 25.6 MB
__device__ float    g_score[NE_TOT * HEADS];     // 13.6 MB (scores, then exp weights in-place)
__device__ unsigned g_smax[N_NODES * HEADS];     // ordered-uint float max
__device__ float    g_denom[N_NODES * HEADS];

// order-preserving float<->uint mapping so atomicMax(unsigned) == float max
__device__ __forceinline__ unsigned f2ord(float f) {
    unsigned u = __float_as_uint(f);
    return (u & 0x80000000u) ? ~u : (u | 0x80000000u);
}
__device__ __forceinline__ float ord2f(unsigned u) {
    return (u & 0x80000000u) ? __uint_as_float(u & 0x7FFFFFFFu) : __uint_as_float(~u);
}

__device__ __forceinline__ float lrelu(float f) {
    return f > 0.f ? f : NEG_SLOPE * f;
}

// ---------------- kernel 0: init scratch + zero output accumulator --------------
__global__ void k_init(float* __restrict__ out) {
    int tid = blockIdx.x * blockDim.x + threadIdx.x;
    int stride = gridDim.x * blockDim.x;
    const unsigned NEG_INF_ORD = f2ord(-CUDART_INF_F);
    for (int i = tid; i < N_NODES * HEADS; i += stride) {
        g_smax[i] = NEG_INF_ORD;
        g_denom[i] = 0.f;
    }
    for (int i = tid; i < N_NODES * OUT_CH; i += stride) {
        out[i] = 0.f;
    }
}

// ---------------- kernel 1: fused dual GEMM  xl = x@Wl+bl, xr = x@Wr+br ----------
// block: 512 threads (128 x 4), 32 nodes per block
#define GN 32
__global__ __launch_bounds__(512) void k_gemm_dual(
    const float* __restrict__ x,
    const float* __restrict__ Wl, const float* __restrict__ bl,
    const float* __restrict__ Wr, const float* __restrict__ br)
{
    __shared__ float xs[GN][IN_CH];
    int o  = threadIdx.x;            // 0..127 output channel
    int ty = threadIdx.y;            // 0..3
    int tid = ty * 128 + o;
    int n0 = blockIdx.x * GN;

    #pragma unroll
    for (int i = 0; i < (GN * IN_CH) / 512; i++) {
        int idx = tid + i * 512;
        int r = idx >> 7, c = idx & 127;
        int n = n0 + r;
        xs[r][c] = (n < N_NODES) ? x[n * IN_CH + c] : 0.f;
    }
    __syncthreads();

    float accl[8], accr[8];
    #pragma unroll
    for (int r = 0; r < 8; r++) { accl[r] = 0.f; accr[r] = 0.f; }

    #pragma unroll 4
    for (int k = 0; k < IN_CH; k++) {
        float wl = Wl[k * OUT_CH + o];
        float wr = Wr[k * OUT_CH + o];
        #pragma unroll
        for (int r = 0; r < 8; r++) {
            float xv = xs[ty + r * 4][k];
            accl[r] = fmaf(xv, wl, accl[r]);
            accr[r] = fmaf(xv, wr, accr[r]);
        }
    }

    float bbl = bl[o], bbr = br[o];
    #pragma unroll
    for (int r = 0; r < 8; r++) {
        int n = n0 + ty + r * 4;
        if (n < N_NODES) {
            g_xl[n * OUT_CH + o] = accl[r] + bbl;
            g_xr[n * OUT_CH + o] = accr[r] + bbr;
        }
    }
}

// ---------------- kernel 2: per-edge attention score + segment max (atomic) -----
// one warp per edge (incl. self loops)
__global__ __launch_bounds__(256) void k_edge_score(
    const int* __restrict__ ei, const float* __restrict__ att)
{
    int warp = (blockIdx.x * blockDim.x + threadIdx.x) >> 5;
    int lane = threadIdx.x & 31;
    if (warp >= NE_TOT) return;

    int src, dst;
    if (warp < N_EDGES) { src = ei[warp]; dst = ei[N_EDGES + warp]; }
    else                { src = dst = warp - N_EDGES; }

    float4 a  = *reinterpret_cast<const float4*>(att  + lane * 4);
    float4 vl = *reinterpret_cast<const float4*>(g_xl + (size_t)src * OUT_CH + lane * 4);
    float4 vr = *reinterpret_cast<const float4*>(g_xr + (size_t)dst * OUT_CH + lane * 4);

    float s = a.x * lrelu(vl.x + vr.x)
            + a.y * lrelu(vl.y + vr.y)
            + a.z * lrelu(vl.z + vr.z)
            + a.w * lrelu(vl.w + vr.w);

    // reduce within each 8-lane group (one head per group)
    s += __shfl_xor_sync(0xFFFFFFFFu, s, 1);
    s += __shfl_xor_sync(0xFFFFFFFFu, s, 2);
    s += __shfl_xor_sync(0xFFFFFFFFu, s, 4);

    if ((lane & 7) == 0) {
        int h = lane >> 3;
        g_score[(size_t)warp * HEADS + h] = s;
        atomicMax(&g_smax[dst * HEADS + h], f2ord(s));
    }
}

// ---------------- kernel 3: exp(score - max), accumulate denom ------------------
// one thread per (edge, head)
__global__ __launch_bounds__(256) void k_edge_exp(const int* __restrict__ ei)
{
    int tid = blockIdx.x * blockDim.x + threadIdx.x;
    if (tid >= NE_TOT * HEADS) return;
    int e = tid >> 2;
    int h = tid & 3;
    int dst = (e < N_EDGES) ? ei[N_EDGES + e] : (e - N_EDGES);
    float m = ord2f(g_smax[dst * HEADS + h]);
    float w = __expf(g_score[tid] - m);
    g_score[tid] = w;   // in place: score -> weight
    atomicAdd(&g_denom[dst * HEADS + h], w);
}

// ---------------- kernel 4: weighted scatter of messages ------------------------
// one warp per edge, float4 vector atomics into out accumulator
__global__ __launch_bounds__(256) void k_edge_scatter(
    const int* __restrict__ ei, float* __restrict__ out)
{
    int warp = (blockIdx.x * blockDim.x + threadIdx.x) >> 5;
    int lane = threadIdx.x & 31;
    if (warp >= NE_TOT) return;

    int src, dst;
    if (warp < N_EDGES) { src = ei[warp]; dst = ei[N_EDGES + warp]; }
    else                { src = dst = warp - N_EDGES; }

    int h = lane >> 3;
    float w = g_score[(size_t)warp * HEADS + h];
    float d = g_denom[dst * HEADS + h];
    float alpha = w / d;

    float4 vl = *reinterpret_cast<const float4*>(g_xl + (size_t)src * OUT_CH + lane * 4);
    float4 m;
    m.x = alpha * vl.x; m.y = alpha * vl.y; m.z = alpha * vl.z; m.w = alpha * vl.w;

#if __CUDA_ARCH__ >= 900
    atomicAdd(reinterpret_cast<float4*>(out + (size_t)dst * OUT_CH + lane * 4), m);
#else
    float* p = out + (size_t)dst * OUT_CH + lane * 4;
    atomicAdd(p + 0, m.x); atomicAdd(p + 1, m.y);
    atomicAdd(p + 2, m.z); atomicAdd(p + 3, m.w);
#endif
}

// ---------------- kernel 5: bias + SiLU + LayerNorm (in-place on out) -----------
// one warp per node
__global__ __launch_bounds__(256) void k_epilogue(
    float* __restrict__ out,
    const float* __restrict__ bias,
    const float* __restrict__ gamma,
    const float* __restrict__ beta)
{
    int warp = (blockIdx.x * blockDim.x + threadIdx.x) >> 5;
    int lane = threadIdx.x & 31;
    if (warp >= N_NODES) return;

    float4 v = *reinterpret_cast<const float4*>(out + (size_t)warp * OUT_CH + lane * 4);
    float4 b = *reinterpret_cast<const float4*>(bias + lane * 4);
    v.x += b.x; v.y += b.y; v.z += b.z; v.w += b.w;

    // SiLU
    v.x = v.x / (1.f + __expf(-v.x));
    v.y = v.y / (1.f + __expf(-v.y));
    v.z = v.z / (1.f + __expf(-v.z));
    v.w = v.w / (1.f + __expf(-v.w));

    float sum = v.x + v.y + v.z + v.w;
    float sq  = v.x * v.x + v.y * v.y + v.z * v.z + v.w * v.w;
    #pragma unroll
    for (int off = 16; off; off >>= 1) {
        sum += __shfl_xor_sync(0xFFFFFFFFu, sum, off);
        sq  += __shfl_xor_sync(0xFFFFFFFFu, sq,  off);
    }
    float mu = sum * (1.f / OUT_CH);
    float var = sq * (1.f / OUT_CH) - mu * mu;
    float rstd = rsqrtf(var + LN_EPS);

    float4 g = *reinterpret_cast<const float4*>(gamma + lane * 4);
    float4 be = *reinterpret_cast<const float4*>(beta + lane * 4);
    float4 r;
    r.x = (v.x - mu) * rstd * g.x + be.x;
    r.y = (v.y - mu) * rstd * g.y + be.y;
    r.z = (v.z - mu) * rstd * g.z + be.z;
    r.w = (v.w - mu) * rstd * g.w + be.w;
    *reinterpret_cast<float4*>(out + (size_t)warp * OUT_CH + lane * 4) = r;
}

// ---------------- launcher -------------------------------------------------------
extern "C" void kernel_launch(void* const* d_in, const int* in_sizes, int n_in,
                              void* d_out, int out_size)
{
    const float* x    = (const float*)d_in[0];
    const int*   ei   = (const int*)  d_in[1];   // edge_index [2, N_EDGES] (int32)
    const float* Wl   = (const float*)d_in[2];
    const float* bl   = (const float*)d_in[3];
    const float* Wr   = (const float*)d_in[4];
    const float* br   = (const float*)d_in[5];
    const float* att  = (const float*)d_in[6];
    const float* bias = (const float*)d_in[7];
    const float* gam  = (const float*)d_in[8];
    const float* bet  = (const float*)d_in[9];
    float* out = (float*)d_out;

    // 0: init
    k_init<<<512, 256>>>(out);

    // 1: dual GEMM
    k_gemm_dual<<<(N_NODES + GN - 1) / GN, dim3(128, 4)>>>(x, Wl, bl, Wr, br);

    // 2: per-edge scores + segment max  (warp per edge)
    {
        int warps = NE_TOT;
        int blocks = (warps * 32 + 255) / 256;
        k_edge_score<<<blocks, 256>>>(ei, att);
    }

    // 3: exp + denom  (thread per edge-head)
    {
        int threads = NE_TOT * HEADS;
        int blocks = (threads + 255) / 256;
        k_edge_exp<<<blocks, 256>>>(ei);
    }

    // 4: weighted scatter  (warp per edge)
    {
        int warps = NE_TOT;
        int blocks = (warps * 32 + 255) / 256;
        k_edge_scatter<<<blocks, 256>>>(ei, out);
    }

    // 5: epilogue  (warp per node)
    {
        int warps = N_NODES;
        int blocks = (warps * 32 + 255) / 256;
        k_epilogue<<<blocks, 256>>>(out, bias, gam, bet);
    }
}

// round 2
// speedup vs baseline: 1.7214x; 1.7214x over previous
#include <cuda_runtime.h>
#include <cuda_bf16.h>

#define N_NODES 50000
#define N_EDGES 800000
#define NE_TOT  (N_EDGES + N_NODES)   // edges + self loops = 850000
#define IN_CH   128
#define OUT_CH  128
#define HEADS   4
#define HEAD_DIM 32
#define NEG_SLOPE 0.2f
#define LN_EPS 1e-5f

#define SCAN_B 512
#define NTILES ((N_NODES + SCAN_B - 1) / SCAN_B)   // 98

// ---------------- scratch (static device arrays) --------------------------------
__device__ float g_xl[N_NODES * OUT_CH];      // 25.6 MB
__device__ float g_xr[N_NODES * OUT_CH];      // 25.6 MB
__device__ int   g_cnt[N_NODES];              // in-degree (incl. self loop)
__device__ int   g_fill[N_NODES];             // fill cursor
__device__ int   g_rowptr[N_NODES + 1];       // CSR row pointers
__device__ int   g_tilesum[NTILES];
__device__ int   g_tilebase[NTILES];
__device__ int   g_csr[NE_TOT];               // src node per CSR slot (sorted by dst)

__device__ __forceinline__ float lrelu(float f) {
    return f > 0.f ? f : NEG_SLOPE * f;
}

// ---------------- kernel 0: init counters ---------------------------------------
__global__ void k_init() {
    int i = blockIdx.x * blockDim.x + threadIdx.x;
    if (i < N_NODES) {
        g_cnt[i] = 1;      // self loop pre-counted
        g_fill[i] = 0;
    }
}

// ---------------- kernel 1: fused dual GEMM  xl = x@Wl+bl, xr = x@Wr+br ----------
#define GN 32
__global__ __launch_bounds__(512) void k_gemm_dual(
    const float* __restrict__ x,
    const float* __restrict__ Wl, const float* __restrict__ bl,
    const float* __restrict__ Wr, const float* __restrict__ br)
{
    __shared__ float xs[GN][IN_CH];
    int o  = threadIdx.x;            // 0..127 output channel
    int ty = threadIdx.y;            // 0..3
    int tid = ty * 128 + o;
    int n0 = blockIdx.x * GN;

    #pragma unroll
    for (int i = 0; i < (GN * IN_CH) / 512; i++) {
        int idx = tid + i * 512;
        int r = idx >> 7, c = idx & 127;
        int n = n0 + r;
        xs[r][c] = (n < N_NODES) ? x[n * IN_CH + c] : 0.f;
    }
    __syncthreads();

    float accl[8], accr[8];
    #pragma unroll
    for (int r = 0; r < 8; r++) { accl[r] = 0.f; accr[r] = 0.f; }

    #pragma unroll 4
    for (int k = 0; k < IN_CH; k++) {
        float wl = Wl[k * OUT_CH + o];
        float wr = Wr[k * OUT_CH + o];
        #pragma unroll
        for (int r = 0; r < 8; r++) {
            float xv = xs[ty + r * 4][k];
            accl[r] = fmaf(xv, wl, accl[r]);
            accr[r] = fmaf(xv, wr, accr[r]);
        }
    }

    float bbl = bl[o], bbr = br[o];
    #pragma unroll
    for (int r = 0; r < 8; r++) {
        int n = n0 + ty + r * 4;
        if (n < N_NODES) {
            g_xl[n * OUT_CH + o] = accl[r] + bbl;
            g_xr[n * OUT_CH + o] = accr[r] + bbr;
        }
    }
}

// ---------------- kernel 2: histogram of destination degrees --------------------
__global__ __launch_bounds__(256) void k_hist(const int* __restrict__ ei) {
    int e = blockIdx.x * blockDim.x + threadIdx.x;
    if (e < N_EDGES) atomicAdd(&g_cnt[ei[N_EDGES + e]], 1);
}

// ---------------- kernels 3a/3b/3c: exclusive scan of g_cnt -> g_rowptr ---------
__global__ __launch_bounds__(SCAN_B) void k_scan1() {
    __shared__ int sh[SCAN_B];
    int t = blockIdx.x, tid = threadIdx.x;
    int i = t * SCAN_B + tid;
    int v = (i < N_NODES) ? g_cnt[i] : 0;
    sh[tid] = v;
    __syncthreads();
    #pragma unroll
    for (int off = 1; off < SCAN_B; off <<= 1) {
        int add = (tid >= off) ? sh[tid - off] : 0;
        __syncthreads();
        sh[tid] += add;
        __syncthreads();
    }
    if (i < N_NODES) g_rowptr[i] = sh[tid] - v;     // exclusive within tile
    if (tid == SCAN_B - 1) g_tilesum[t] = sh[tid];
}

__global__ void k_scan2() {
    if (threadIdx.x == 0 && blockIdx.x == 0) {
        int run = 0;
        for (int t = 0; t < NTILES; t++) { g_tilebase[t] = run; run += g_tilesum[t]; }
        g_rowptr[N_NODES] = run;   // == NE_TOT
    }
}

__global__ __launch_bounds__(SCAN_B) void k_scan3() {
    int i = blockIdx.x * SCAN_B + threadIdx.x;
    if (i < N_NODES) g_rowptr[i] += g_tilebase[blockIdx.x];
}

// ---------------- kernel 4: fill CSR (edges + self loops) -----------------------
__global__ __launch_bounds__(256) void k_fill(const int* __restrict__ ei) {
    int t = blockIdx.x * blockDim.x + threadIdx.x;
    if (t >= NE_TOT) return;
    int src, dst;
    if (t < N_EDGES) { src = ei[t]; dst = ei[N_EDGES + t]; }
    else             { src = dst = t - N_EDGES; }
    int pos = g_rowptr[dst] + atomicAdd(&g_fill[dst], 1);
    g_csr[pos] = src;
}

// ---------------- kernel 5: fused attention aggregate + SiLU + LayerNorm --------
// one warp per destination node; single gather pass over incoming edges
__global__ __launch_bounds__(256) void k_aggregate(
    const float* __restrict__ att,
    const float* __restrict__ bias,
    const float* __restrict__ gamma,
    const float* __restrict__ beta,
    float* __restrict__ out)
{
    int warp = (blockIdx.x * blockDim.x + threadIdx.x) >> 5;
    int lane = threadIdx.x & 31;
    if (warp >= N_NODES) return;

    // lane covers channels [lane*4, lane*4+4); head = lane>>3
    float4 a   = *reinterpret_cast<const float4*>(att + lane * 4);
    float4 xr4 = *reinterpret_cast<const float4*>(g_xr + (size_t)warp * OUT_CH + lane * 4);

    int base = g_rowptr[warp];
    int end  = g_rowptr[warp + 1];

    float4 acc = make_float4(0.f, 0.f, 0.f, 0.f);
    float denom = 0.f;

    for (int k = base; k < end; k++) {
        int src = g_csr[k];                       // broadcast load
        float4 vl = *reinterpret_cast<const float4*>(g_xl + (size_t)src * OUT_CH + lane * 4);

        float s = a.x * lrelu(vl.x + xr4.x)
                + a.y * lrelu(vl.y + xr4.y)
                + a.z * lrelu(vl.z + xr4.z)
                + a.w * lrelu(vl.w + xr4.w);
        // reduce+broadcast within each 8-lane head group
        s += __shfl_xor_sync(0xFFFFFFFFu, s, 1);
        s += __shfl_xor_sync(0xFFFFFFFFu, s, 2);
        s += __shfl_xor_sync(0xFFFFFFFFu, s, 4);

        float w = __expf(s);                      // no max-subtraction needed (|s| small)
        denom += w;
        acc.x = fmaf(w, vl.x, acc.x);
        acc.y = fmaf(w, vl.y, acc.y);
        acc.z = fmaf(w, vl.z, acc.z);
        acc.w = fmaf(w, vl.w, acc.w);
    }

    float inv = __frcp_rn(denom);
    float4 b = *reinterpret_cast<const float4*>(bias + lane * 4);
    float4 v;
    v.x = fmaf(acc.x, inv, b.x);
    v.y = fmaf(acc.y, inv, b.y);
    v.z = fmaf(acc.z, inv, b.z);
    v.w = fmaf(acc.w, inv, b.w);

    // SiLU
    v.x = v.x / (1.f + __expf(-v.x));
    v.y = v.y / (1.f + __expf(-v.y));
    v.z = v.z / (1.f + __expf(-v.z));
    v.w = v.w / (1.f + __expf(-v.w));

    // LayerNorm across the warp (128 channels)
    float sum = v.x + v.y + v.z + v.w;
    float sq  = v.x * v.x + v.y * v.y + v.z * v.z + v.w * v.w;
    #pragma unroll
    for (int off = 16; off; off >>= 1) {
        sum += __shfl_xor_sync(0xFFFFFFFFu, sum, off);
        sq  += __shfl_xor_sync(0xFFFFFFFFu, sq,  off);
    }
    float mu   = sum * (1.f / OUT_CH);
    float var  = sq * (1.f / OUT_CH) - mu * mu;
    float rstd = rsqrtf(var + LN_EPS);

    float4 g  = *reinterpret_cast<const float4*>(gamma + lane * 4);
    float4 be = *reinterpret_cast<const float4*>(beta  + lane * 4);
    float4 r;
    r.x = (v.x - mu) * rstd * g.x + be.x;
    r.y = (v.y - mu) * rstd * g.y + be.y;
    r.z = (v.z - mu) * rstd * g.z + be.z;
    r.w = (v.w - mu) * rstd * g.w + be.w;
    *reinterpret_cast<float4*>(out + (size_t)warp * OUT_CH + lane * 4) = r;
}

// ---------------- launcher -------------------------------------------------------
extern "C" void kernel_launch(void* const* d_in, const int* in_sizes, int n_in,
                              void* d_out, int out_size)
{
    const float* x    = (const float*)d_in[0];
    const int*   ei   = (const int*)  d_in[1];
    const float* Wl   = (const float*)d_in[2];
    const float* bl   = (const float*)d_in[3];
    const float* Wr   = (const float*)d_in[4];
    const float* br   = (const float*)d_in[5];
    const float* att  = (const float*)d_in[6];
    const float* bias = (const float*)d_in[7];
    const float* gam  = (const float*)d_in[8];
    const float* bet  = (const float*)d_in[9];
    float* out = (float*)d_out;

    k_init<<<(N_NODES + 255) / 256, 256>>>();

    k_gemm_dual<<<(N_NODES + GN - 1) / GN, dim3(128, 4)>>>(x, Wl, bl, Wr, br);

    k_hist<<<(N_EDGES + 255) / 256, 256>>>(ei);

    k_scan1<<<NTILES, SCAN_B>>>();
    k_scan2<<<1, 32>>>();
    k_scan3<<<NTILES, SCAN_B>>>();

    k_fill<<<(NE_TOT + 255) / 256, 256>>>(ei);

    k_aggregate<<<(N_NODES * 32 + 255) / 256, 256>>>(att, bias, gam, bet, out);
}

// round 3
// speedup vs baseline: 1.7634x; 1.0244x over previous
#include <cuda_runtime.h>
#include <cuda_bf16.h>

#define N_NODES 50000
#define N_EDGES 800000
#define NE_TOT  (N_EDGES + N_NODES)   // 850000
#define IN_CH   128
#define OUT_CH  128
#define HEADS   4
#define HEAD_DIM 32
#define NEG_SLOPE 0.2f
#define LN_EPS 1e-5f

#define SCAN_B 512
#define NTILES ((N_NODES + SCAN_B - 1) / SCAN_B)   // 98

// ---------------- scratch ---------------------------------------------------------
__device__ float g_xl[N_NODES * OUT_CH];
__device__ float g_xr[N_NODES * OUT_CH];
__device__ int   g_cnt[N_NODES];
__device__ int   g_fill[N_NODES];
__device__ int   g_rowptr[N_NODES + 1];
__device__ int   g_tilesum[NTILES];
__device__ int   g_tilebase[NTILES];
__device__ int   g_csr[NE_TOT];

__device__ __forceinline__ float lrelu(float f) {
    return f > 0.f ? f : NEG_SLOPE * f;
}

// ---- packed f32x2 helpers (PTX-only; ptxas never auto-fuses FFMA2) --------------
typedef unsigned long long ull;
__device__ __forceinline__ ull pack2(float lo, float hi) {
    ull r; asm("mov.b64 %0, {%1, %2};" : "=l"(r) : "f"(lo), "f"(hi)); return r;
}
__device__ __forceinline__ void fma2(ull& d, ull a, ull b) {
    asm("fma.rn.f32x2 %0, %1, %2, %0;" : "+l"(d) : "l"(a), "l"(b));
}
__device__ __forceinline__ float2 unpack2(ull v) {
    float2 f; asm("mov.b64 {%0, %1}, %2;" : "=f"(f.x), "=f"(f.y) : "l"(v)); return f;
}

// ---------------- kernel 0: init counters ----------------------------------------
__global__ void k_init() {
    int i = blockIdx.x * blockDim.x + threadIdx.x;
    if (i < N_NODES) {
        g_cnt[i] = 1;      // self loop pre-counted
        g_fill[i] = 0;
    }
}

// ---------------- kernel 1: fused dual GEMM with packed f32x2 FMA -----------------
// block (64,4) = 256 threads; 32 nodes per block; thread -> channel pair (2tx,2tx+1)
#define GN 32
__global__ __launch_bounds__(256) void k_gemm_dual(
    const float* __restrict__ x,
    const float* __restrict__ Wl, const float* __restrict__ bl,
    const float* __restrict__ Wr, const float* __restrict__ br)
{
    __shared__ float xs[GN][IN_CH];
    int tx = threadIdx.x;            // 0..63
    int ty = threadIdx.y;            // 0..3
    int tid = ty * 64 + tx;
    int n0 = blockIdx.x * GN;
    int c0 = tx * 2;

    // load x tile: 4096 floats = 1024 float4, 256 threads -> 4 float4 each
    #pragma unroll
    for (int i = 0; i < 4; i++) {
        int idx = tid + i * 256;          // float4 index
        int r = idx >> 5, c = idx & 31;   // 32 float4 per row
        int n = n0 + r;
        float4 v = make_float4(0.f, 0.f, 0.f, 0.f);
        if (n < N_NODES) v = *reinterpret_cast<const float4*>(x + (size_t)n * IN_CH + c * 4);
        *reinterpret_cast<float4*>(&xs[r][c * 4]) = v;
    }
    __syncthreads();

    ull accl[8], accr[8];
    #pragma unroll
    for (int r = 0; r < 8; r++) { accl[r] = 0ull; accr[r] = 0ull; }

    #pragma unroll 2
    for (int k = 0; k < IN_CH; k += 2) {
        ull wl0 = *reinterpret_cast<const ull*>(Wl + (size_t)k * OUT_CH + c0);
        ull wl1 = *reinterpret_cast<const ull*>(Wl + (size_t)(k + 1) * OUT_CH + c0);
        ull wr0 = *reinterpret_cast<const ull*>(Wr + (size_t)k * OUT_CH + c0);
        ull wr1 = *reinterpret_cast<const ull*>(Wr + (size_t)(k + 1) * OUT_CH + c0);
        #pragma unroll
        for (int r = 0; r < 8; r++) {
            float2 xv = *reinterpret_cast<const float2*>(&xs[ty + r * 4][k]);
            ull x0 = pack2(xv.x, xv.x);
            ull x1 = pack2(xv.y, xv.y);
            fma2(accl[r], x0, wl0);
            fma2(accl[r], x1, wl1);
            fma2(accr[r], x0, wr0);
            fma2(accr[r], x1, wr1);
        }
    }

    float2 b_l = *reinterpret_cast<const float2*>(bl + c0);
    float2 b_r = *reinterpret_cast<const float2*>(br + c0);
    #pragma unroll
    for (int r = 0; r < 8; r++) {
        int n = n0 + ty + r * 4;
        if (n < N_NODES) {
            float2 vl = unpack2(accl[r]);
            float2 vr = unpack2(accr[r]);
            vl.x += b_l.x; vl.y += b_l.y;
            vr.x += b_r.x; vr.y += b_r.y;
            *reinterpret_cast<float2*>(g_xl + (size_t)n * OUT_CH + c0) = vl;
            *reinterpret_cast<float2*>(g_xr + (size_t)n * OUT_CH + c0) = vr;
        }
    }
}

// ---------------- kernel 2: histogram of destination degrees ----------------------
__global__ __launch_bounds__(256) void k_hist(const int* __restrict__ ei) {
    int e = blockIdx.x * blockDim.x + threadIdx.x;
    if (e < N_EDGES) atomicAdd(&g_cnt[ei[N_EDGES + e]], 1);
}

// ---------------- scan: tile scan, tile-base scan (parallel), apply ---------------
__global__ __launch_bounds__(SCAN_B) void k_scan1() {
    __shared__ int sh[SCAN_B];
    int t = blockIdx.x, tid = threadIdx.x;
    int i = t * SCAN_B + tid;
    int v = (i < N_NODES) ? g_cnt[i] : 0;
    sh[tid] = v;
    __syncthreads();
    #pragma unroll
    for (int off = 1; off < SCAN_B; off <<= 1) {
        int add = (tid >= off) ? sh[tid - off] : 0;
        __syncthreads();
        sh[tid] += add;
        __syncthreads();
    }
    if (i < N_NODES) g_rowptr[i] = sh[tid] - v;     // exclusive within tile
    if (tid == SCAN_B - 1) g_tilesum[t] = sh[tid];
}

// parallel scan of the 98 tile sums (128 threads, 4 warps)
__global__ __launch_bounds__(128) void k_scan2() {
    int t = threadIdx.x;
    int lane = t & 31, w = t >> 5;
    int v = (t < NTILES) ? g_tilesum[t] : 0;
    int inc = v;
    #pragma unroll
    for (int off = 1; off < 32; off <<= 1) {
        int n = __shfl_up_sync(0xFFFFFFFFu, inc, off);
        if (lane >= off) inc += n;
    }
    __shared__ int wsum[4];
    if (lane == 31) wsum[w] = inc;
    __syncthreads();
    int prefix = 0;
    #pragma unroll
    for (int j = 0; j < 4; j++) if (j < w) prefix += wsum[j];
    inc += prefix;
    if (t < NTILES) g_tilebase[t] = inc - v;        // exclusive
    if (t == NTILES - 1) g_rowptr[N_NODES] = inc;   // total == NE_TOT
}

__global__ __launch_bounds__(SCAN_B) void k_scan3() {
    int i = blockIdx.x * SCAN_B + threadIdx.x;
    if (i < N_NODES) g_rowptr[i] += g_tilebase[blockIdx.x];
}

// ---------------- kernel 4: fill CSR ----------------------------------------------
__global__ __launch_bounds__(256) void k_fill(const int* __restrict__ ei) {
    int t = blockIdx.x * blockDim.x + threadIdx.x;
    if (t >= NE_TOT) return;
    int src, dst;
    if (t < N_EDGES) { src = ei[t]; dst = ei[N_EDGES + t]; }
    else             { src = dst = t - N_EDGES; }
    int pos = g_rowptr[dst] + atomicAdd(&g_fill[dst], 1);
    g_csr[pos] = src;
}

// ---------------- kernel 5: fused attention aggregate + SiLU + LayerNorm ----------
__global__ __launch_bounds__(256) void k_aggregate(
    const float* __restrict__ att,
    const float* __restrict__ bias,
    const float* __restrict__ gamma,
    const float* __restrict__ beta,
    float* __restrict__ out)
{
    int warp = (blockIdx.x * blockDim.x + threadIdx.x) >> 5;
    int lane = threadIdx.x & 31;
    if (warp >= N_NODES) return;

    float4 a   = *reinterpret_cast<const float4*>(att + lane * 4);
    float4 xr4 = *reinterpret_cast<const float4*>(g_xr + (size_t)warp * OUT_CH + lane * 4);

    int base = g_rowptr[warp];
    int end  = g_rowptr[warp + 1];

    float4 acc = make_float4(0.f, 0.f, 0.f, 0.f);
    float denom = 0.f;

    for (int k = base; k < end; k++) {
        int src = g_csr[k];
        float4 vl = *reinterpret_cast<const float4*>(g_xl + (size_t)src * OUT_CH + lane * 4);

        float s = a.x * lrelu(vl.x + xr4.x)
                + a.y * lrelu(vl.y + xr4.y)
                + a.z * lrelu(vl.z + xr4.z)
                + a.w * lrelu(vl.w + xr4.w);
        s += __shfl_xor_sync(0xFFFFFFFFu, s, 1);
        s += __shfl_xor_sync(0xFFFFFFFFu, s, 2);
        s += __shfl_xor_sync(0xFFFFFFFFu, s, 4);

        float w = __expf(s);
        denom += w;
        acc.x = fmaf(w, vl.x, acc.x);
        acc.y = fmaf(w, vl.y, acc.y);
        acc.z = fmaf(w, vl.z, acc.z);
        acc.w = fmaf(w, vl.w, acc.w);
    }

    float inv = __frcp_rn(denom);
    float4 b = *reinterpret_cast<const float4*>(bias + lane * 4);
    float4 v;
    v.x = fmaf(acc.x, inv, b.x);
    v.y = fmaf(acc.y, inv, b.y);
    v.z = fmaf(acc.z, inv, b.z);
    v.w = fmaf(acc.w, inv, b.w);

    v.x = v.x / (1.f + __expf(-v.x));
    v.y = v.y / (1.f + __expf(-v.y));
    v.z = v.z / (1.f + __expf(-v.z));
    v.w = v.w / (1.f + __expf(-v.w));

    float sum = v.x + v.y + v.z + v.w;
    float sq  = v.x * v.x + v.y * v.y + v.z * v.z + v.w * v.w;
    #pragma unroll
    for (int off = 16; off; off >>= 1) {
        sum += __shfl_xor_sync(0xFFFFFFFFu, sum, off);
        sq  += __shfl_xor_sync(0xFFFFFFFFu, sq,  off);
    }
    float mu   = sum * (1.f / OUT_CH);
    float var  = sq * (1.f / OUT_CH) - mu * mu;
    float rstd = rsqrtf(var + LN_EPS);

    float4 g  = *reinterpret_cast<const float4*>(gamma + lane * 4);
    float4 be = *reinterpret_cast<const float4*>(beta  + lane * 4);
    float4 r;
    r.x = (v.x - mu) * rstd * g.x + be.x;
    r.y = (v.y - mu) * rstd * g.y + be.y;
    r.z = (v.z - mu) * rstd * g.z + be.z;
    r.w = (v.w - mu) * rstd * g.w + be.w;
    *reinterpret_cast<float4*>(out + (size_t)warp * OUT_CH + lane * 4) = r;
}

// ---------------- launcher ----------------------------------------------------------
extern "C" void kernel_launch(void* const* d_in, const int* in_sizes, int n_in,
                              void* d_out, int out_size)
{
    const float* x    = (const float*)d_in[0];
    const int*   ei   = (const int*)  d_in[1];
    const float* Wl   = (const float*)d_in[2];
    const float* bl   = (const float*)d_in[3];
    const float* Wr   = (const float*)d_in[4];
    const float* br   = (const float*)d_in[5];
    const float* att  = (const float*)d_in[6];
    const float* bias = (const float*)d_in[7];
    const float* gam  = (const float*)d_in[8];
    const float* bet  = (const float*)d_in[9];
    float* out = (float*)d_out;

    k_init<<<(N_NODES + 255) / 256, 256>>>();

    k_gemm_dual<<<(N_NODES + GN - 1) / GN, dim3(64, 4)>>>(x, Wl, bl, Wr, br);

    k_hist<<<(N_EDGES + 255) / 256, 256>>>(ei);

    k_scan1<<<NTILES, SCAN_B>>>();
    k_scan2<<<1, 128>>>();
    k_scan3<<<NTILES, SCAN_B>>>();

    k_fill<<<(NE_TOT + 255) / 256, 256>>>(ei);

    k_aggregate<<<(N_NODES * 32 + 255) / 256, 256>>>(att, bias, gam, bet, out);
}